// round 7
// baseline (speedup 1.0000x reference)
#include <cuda_runtime.h>
#include <math.h>

#define N_TOK 2048
#define HDIM  1024
#define FDIM  1024
#define NE    8
#define TOPK  2
#define SLOTS (NE * N_TOK)

// ---------------- device scratch (static: no allocations allowed) -----------
__device__ int   d_mask;                         // primary expert bitmask
__device__ int   d_cnt[NE];                      // tokens per expert
__device__ int   d_map[NE];                      // SERE expert remap
__device__ int   d_tok[SLOTS];                   // token index per (expert, slot)
__device__ int   d_top_i[N_TOK * TOPK];
__device__ float d_top_w[N_TOK * TOPK];
__device__ int   d_pair_slot[N_TOK * TOPK];      // global slot per token pair (-1 if unused)
__device__ float d_pair_w[N_TOK * TOPK];
__device__ float d_gu  [(size_t)SLOTS * 2 * FDIM];   // 128 MB
__device__ float d_hmid[(size_t)SLOTS * FDIM];       // 64 MB
__device__ float d_y   [(size_t)SLOTS * HDIM];       // 64 MB

// ---------------- tiny setup kernels ----------------------------------------
__global__ void init_kernel() {
    if (threadIdx.x == 0) d_mask = 0;
}

// One block (128 threads) per token: logits -> softmax -> top2 -> normalize.
__global__ void router_kernel(const float* __restrict__ x,
                              const float* __restrict__ gw) {
    int n   = blockIdx.x;
    int tid = threadIdx.x;                 // 128 threads
    const float* xr = x + (size_t)n * HDIM;

    float p[NE];
#pragma unroll
    for (int e = 0; e < NE; ++e) p[e] = 0.f;

    for (int h = tid; h < HDIM; h += 128) {
        float xv = xr[h];
#pragma unroll
        for (int e = 0; e < NE; ++e)
            p[e] = fmaf(xv, gw[e * HDIM + h], p[e]);
    }
#pragma unroll
    for (int e = 0; e < NE; ++e)
#pragma unroll
        for (int o = 16; o > 0; o >>= 1)
            p[e] += __shfl_xor_sync(0xffffffffu, p[e], o);

    __shared__ float sh[NE][4];
    int w = tid >> 5, l = tid & 31;
    if (l == 0)
#pragma unroll
        for (int e = 0; e < NE; ++e) sh[e][w] = p[e];
    __syncthreads();

    if (tid == 0) {
        float lg[NE];
#pragma unroll
        for (int e = 0; e < NE; ++e)
            lg[e] = sh[e][0] + sh[e][1] + sh[e][2] + sh[e][3];
        float mx = lg[0];
#pragma unroll
        for (int e = 1; e < NE; ++e) mx = fmaxf(mx, lg[e]);
        float pr[NE], s = 0.f;
#pragma unroll
        for (int e = 0; e < NE; ++e) { pr[e] = expf(lg[e] - mx); s += pr[e]; }
        float inv = 1.f / s;
#pragma unroll
        for (int e = 0; e < NE; ++e) pr[e] *= inv;

        int i0 = 0;
#pragma unroll
        for (int e = 1; e < NE; ++e) if (pr[e] > pr[i0]) i0 = e;
        int i1 = -1;
#pragma unroll
        for (int e = 0; e < NE; ++e)
            if (e != i0 && (i1 < 0 || pr[e] > pr[i1])) i1 = e;

        float w0 = pr[i0], w1 = pr[i1];
        float den = fmaxf(w0 + w1, 1e-12f);
        w0 /= den; w1 /= den;

        d_top_i[2 * n]     = i0;
        d_top_i[2 * n + 1] = i1;
        d_top_w[2 * n]     = w0;
        d_top_w[2 * n + 1] = w1;
        atomicOr(&d_mask, 1 << i0);
    }
}

// SERE reroute table (one warp); also zeroes per-expert counters.
__global__ void map_kernel(const float* __restrict__ sim) {
    int e = threadIdx.x;
    if (e < NE) {
        d_cnt[e] = 0;
        int mask = d_mask;
        int m;
        if ((mask >> e) & 1) {
            m = e;
        } else {
            float best = -INFINITY; int bj = -1;
#pragma unroll
            for (int j = 0; j < NE; ++j) {
                if ((mask >> j) & 1) {
                    float s = sim[e * NE + j];
                    if (s > best) { best = s; bj = j; }   // first max kept (argmax tie rule)
                }
            }
            m = (bj >= 0 && best >= 0.7f) ? bj : e;
        }
        d_map[e] = m;
    }
}

// Apply reroute, merge duplicate slots, assign compact per-expert rows.
__global__ void assign_kernel() {
    int n = blockIdx.x * blockDim.x + threadIdx.x;
    if (n >= N_TOK) return;
    int   i0 = d_top_i[2 * n],     i1 = d_top_i[2 * n + 1];
    float w0 = d_top_w[2 * n],     w1 = d_top_w[2 * n + 1];
    int   e0 = d_map[i0],          e1 = d_map[i1];

    if (e0 == e1) {
        int idx = atomicAdd(&d_cnt[e0], 1);
        int s   = e0 * N_TOK + idx;
        d_tok[s] = n;
        d_pair_slot[2 * n]     = s;   d_pair_w[2 * n]     = w0 + w1;
        d_pair_slot[2 * n + 1] = -1;  d_pair_w[2 * n + 1] = 0.f;
    } else {
        int idx0 = atomicAdd(&d_cnt[e0], 1);
        int idx1 = atomicAdd(&d_cnt[e1], 1);
        int s0 = e0 * N_TOK + idx0, s1 = e1 * N_TOK + idx1;
        d_tok[s0] = n;
        d_tok[s1] = n;
        d_pair_slot[2 * n]     = s0;  d_pair_w[2 * n]     = w0;
        d_pair_slot[2 * n + 1] = s1;  d_pair_w[2 * n + 1] = w1;
    }
}

// ---------------- SGEMM: C[m,j] = sum_k A[m,k] * W[e,j,k]  (both K-major) ----
// FIRST=true : A = x rows gathered via d_tok,  W = gate_up_proj, C = d_gu  (NCOLS=2048)
// FIRST=false: A = d_hmid rows (compact),      W = down_proj,    C = d_y   (NCOLS=1024)
#define BM 128
#define BN 128
#define BK 8

template <bool FIRST>
__global__ __launch_bounds__(256, 2)
void gemm_kernel(const float* __restrict__ Ain, const float* __restrict__ W) {
    constexpr int NCOLS = FIRST ? (2 * FDIM) : HDIM;
    constexpr int KDIM  = FIRST ? HDIM : FDIM;

    int e   = blockIdx.z;
    int cnt = d_cnt[e];
    int m0  = blockIdx.y * BM;
    if (m0 >= cnt) return;
    int j0  = blockIdx.x * BN;

    const float* We = W + (size_t)e * NCOLS * KDIM;
    float*       C  = FIRST ? d_gu : d_y;

    int tid  = threadIdx.x;
    int lrow = tid >> 1;            // 0..127
    int lk   = (tid & 1) * 4;       // 0 or 4

    // A row pointer for the loader
    int  am     = m0 + lrow;
    bool avalid = (am < cnt);
    const float* arow;
    if (FIRST) {
        int t = avalid ? d_tok[e * N_TOK + am] : 0;
        arow  = Ain + (size_t)t * KDIM;
    } else {
        arow  = d_hmid + (size_t)(e * N_TOK + (avalid ? am : 0)) * KDIM;
    }
    const float* brow = We + (size_t)(j0 + lrow) * KDIM;

    __shared__ float As[2][BK][BM];
    __shared__ float Bs[2][BK][BN];

    float acc[8][8];
#pragma unroll
    for (int i = 0; i < 8; ++i)
#pragma unroll
        for (int j = 0; j < 8; ++j) acc[i][j] = 0.f;

    int trow = tid >> 4;            // 0..15  -> rows trow*8..+8
    int tcol = tid & 15;            // 0..15  -> cols tcol*8..+8

    // prologue: k-tile 0
    float4 av = avalid ? *(const float4*)(arow + lk) : make_float4(0.f, 0.f, 0.f, 0.f);
    float4 bv = *(const float4*)(brow + lk);
    As[0][lk + 0][lrow] = av.x; As[0][lk + 1][lrow] = av.y;
    As[0][lk + 2][lrow] = av.z; As[0][lk + 3][lrow] = av.w;
    Bs[0][lk + 0][lrow] = bv.x; Bs[0][lk + 1][lrow] = bv.y;
    Bs[0][lk + 2][lrow] = bv.z; Bs[0][lk + 3][lrow] = bv.w;
    __syncthreads();

    const int KT = KDIM / BK;
    for (int kt = 0; kt < KT; ++kt) {
        int buf = kt & 1;
        float4 av2 = make_float4(0.f, 0.f, 0.f, 0.f), bv2;
        bool more = (kt + 1 < KT);
        if (more) {
            int kb = (kt + 1) * BK;
            if (avalid) av2 = *(const float4*)(arow + kb + lk);
            bv2 = *(const float4*)(brow + kb + lk);
        }
#pragma unroll
        for (int kk = 0; kk < BK; ++kk) {
            float4 a0 = *(const float4*)&As[buf][kk][trow * 8];
            float4 a1 = *(const float4*)&As[buf][kk][trow * 8 + 4];
            float4 b0 = *(const float4*)&Bs[buf][kk][tcol * 8];
            float4 b1 = *(const float4*)&Bs[buf][kk][tcol * 8 + 4];
            float a[8] = {a0.x, a0.y, a0.z, a0.w, a1.x, a1.y, a1.z, a1.w};
            float b[8] = {b0.x, b0.y, b0.z, b0.w, b1.x, b1.y, b1.z, b1.w};
#pragma unroll
            for (int i = 0; i < 8; ++i)
#pragma unroll
                for (int j = 0; j < 8; ++j)
                    acc[i][j] = fmaf(a[i], b[j], acc[i][j]);
        }
        if (more) {
            int nb = buf ^ 1;
            As[nb][lk + 0][lrow] = av2.x; As[nb][lk + 1][lrow] = av2.y;
            As[nb][lk + 2][lrow] = av2.z; As[nb][lk + 3][lrow] = av2.w;
            Bs[nb][lk + 0][lrow] = bv2.x; Bs[nb][lk + 1][lrow] = bv2.y;
            Bs[nb][lk + 2][lrow] = bv2.z; Bs[nb][lk + 3][lrow] = bv2.w;
            __syncthreads();
        }
    }

    // epilogue
#pragma unroll
    for (int i = 0; i < 8; ++i) {
        int m = m0 + trow * 8 + i;
        if (m < cnt) {
            float* crow = C + (size_t)(e * N_TOK + m) * NCOLS + j0 + tcol * 8;
            *(float4*)(crow)     = make_float4(acc[i][0], acc[i][1], acc[i][2], acc[i][3]);
            *(float4*)(crow + 4) = make_float4(acc[i][4], acc[i][5], acc[i][6], acc[i][7]);
        }
    }
}

// hmid = silu(gate) * up
__global__ void silu_kernel() {
    int e = blockIdx.z;
    int m = blockIdx.y;
    if (m >= d_cnt[e]) return;
    size_t slot = (size_t)(e * N_TOK + m);
    int q = threadIdx.x;               // 256 threads -> 256 float4 = 1024 floats
    const float4 g4 = *(const float4*)&d_gu[slot * (2 * FDIM) + q * 4];
    const float4 u4 = *(const float4*)&d_gu[slot * (2 * FDIM) + FDIM + q * 4];
    float4 r;
    r.x = (g4.x / (1.f + expf(-g4.x))) * u4.x;
    r.y = (g4.y / (1.f + expf(-g4.y))) * u4.y;
    r.z = (g4.z / (1.f + expf(-g4.z))) * u4.z;
    r.w = (g4.w / (1.f + expf(-g4.w))) * u4.w;
    *(float4*)&d_hmid[slot * FDIM + q * 4] = r;
}

// out[n] = w0 * y[slot0] + w1 * y[slot1]
__global__ void combine_kernel(float* __restrict__ out) {
    int n = blockIdx.x;
    int q = threadIdx.x;               // 256 threads -> 1024 floats
    int   s0 = d_pair_slot[2 * n],     s1 = d_pair_slot[2 * n + 1];
    float w0 = d_pair_w[2 * n],        w1 = d_pair_w[2 * n + 1];

    float4 a = *(const float4*)&d_y[(size_t)s0 * HDIM + q * 4];
    float4 r;
    r.x = w0 * a.x; r.y = w0 * a.y; r.z = w0 * a.z; r.w = w0 * a.w;
    if (s1 >= 0) {
        float4 b = *(const float4*)&d_y[(size_t)s1 * HDIM + q * 4];
        r.x = fmaf(w1, b.x, r.x); r.y = fmaf(w1, b.y, r.y);
        r.z = fmaf(w1, b.z, r.z); r.w = fmaf(w1, b.w, r.w);
    }
    *(float4*)&out[(size_t)n * HDIM + q * 4] = r;
}

// ---------------- launcher ---------------------------------------------------
extern "C" void kernel_launch(void* const* d_in, const int* in_sizes, int n_in,
                              void* d_out, int out_size) {
    const float* x   = (const float*)d_in[0];  // [2,1024,1024] -> [2048,1024]
    const float* gw  = (const float*)d_in[1];  // [8,1024]
    const float* gup = (const float*)d_in[2];  // [8,2048,1024]
    const float* dwn = (const float*)d_in[3];  // [8,1024,1024]
    const float* sim = (const float*)d_in[4];  // [8,8]
    float* out = (float*)d_out;                // [2048,1024]

    init_kernel<<<1, 32>>>();
    router_kernel<<<N_TOK, 128>>>(x, gw);
    map_kernel<<<1, 32>>>(sim);
    assign_kernel<<<(N_TOK + 255) / 256, 256>>>();

    // gemm1: gu[slot, 0:2048] = x_gathered @ gate_up^T
    gemm_kernel<true><<<dim3((2 * FDIM) / BN, N_TOK / BM, NE), 256>>>(x, gup);
    silu_kernel<<<dim3(1, N_TOK, NE), 256>>>();
    // gemm2: y[slot, 0:1024] = hmid @ down^T
    gemm_kernel<false><<<dim3(HDIM / BN, N_TOK / BM, NE), 256>>>(nullptr, dwn);
    combine_kernel<<<N_TOK, 256>>>(out);
}

// round 10
// speedup vs baseline: 2.2138x; 2.2138x over previous
#include <cuda_runtime.h>
#include <cuda_bf16.h>
#include <math.h>
#include <stdint.h>

#define N_TOK 2048
#define HDIM  1024
#define FDIM  1024
#define NE    8
#define TOPK  2
#define SLOTS (NE * N_TOK)

// ---------------- device scratch (static: no allocations allowed) -----------
__device__ int   d_mask;
__device__ int   d_cnt[NE];
__device__ int   d_map[NE];
__device__ int   d_tok[SLOTS];
__device__ int   d_top_i[N_TOK * TOPK];
__device__ float d_top_w[N_TOK * TOPK];
__device__ int   d_pair_slot[N_TOK * TOPK];
__device__ float d_pair_w[N_TOK * TOPK];
__device__ float d_gu  [(size_t)SLOTS * 2 * FDIM];
__device__ float d_hmid[(size_t)SLOTS * FDIM];
__device__ float d_y   [(size_t)SLOTS * HDIM];

// ---------------- tiny setup kernels ----------------------------------------
__global__ void init_kernel() {
    if (threadIdx.x == 0) d_mask = 0;
}

__global__ void router_kernel(const float* __restrict__ x,
                              const float* __restrict__ gw) {
    int n   = blockIdx.x;
    int tid = threadIdx.x;
    const float* xr = x + (size_t)n * HDIM;

    float p[NE];
#pragma unroll
    for (int e = 0; e < NE; ++e) p[e] = 0.f;

    for (int h = tid; h < HDIM; h += 128) {
        float xv = xr[h];
#pragma unroll
        for (int e = 0; e < NE; ++e)
            p[e] = fmaf(xv, gw[e * HDIM + h], p[e]);
    }
#pragma unroll
    for (int e = 0; e < NE; ++e)
#pragma unroll
        for (int o = 16; o > 0; o >>= 1)
            p[e] += __shfl_xor_sync(0xffffffffu, p[e], o);

    __shared__ float sh[NE][4];
    int w = tid >> 5, l = tid & 31;
    if (l == 0)
#pragma unroll
        for (int e = 0; e < NE; ++e) sh[e][w] = p[e];
    __syncthreads();

    if (tid == 0) {
        float lg[NE];
#pragma unroll
        for (int e = 0; e < NE; ++e)
            lg[e] = sh[e][0] + sh[e][1] + sh[e][2] + sh[e][3];
        float mx = lg[0];
#pragma unroll
        for (int e = 1; e < NE; ++e) mx = fmaxf(mx, lg[e]);
        float pr[NE], s = 0.f;
#pragma unroll
        for (int e = 0; e < NE; ++e) { pr[e] = expf(lg[e] - mx); s += pr[e]; }
        float inv = 1.f / s;
#pragma unroll
        for (int e = 0; e < NE; ++e) pr[e] *= inv;

        int i0 = 0;
#pragma unroll
        for (int e = 1; e < NE; ++e) if (pr[e] > pr[i0]) i0 = e;
        int i1 = -1;
#pragma unroll
        for (int e = 0; e < NE; ++e)
            if (e != i0 && (i1 < 0 || pr[e] > pr[i1])) i1 = e;

        float w0 = pr[i0], w1 = pr[i1];
        float den = fmaxf(w0 + w1, 1e-12f);
        w0 /= den; w1 /= den;

        d_top_i[2 * n]     = i0;
        d_top_i[2 * n + 1] = i1;
        d_top_w[2 * n]     = w0;
        d_top_w[2 * n + 1] = w1;
        atomicOr(&d_mask, 1 << i0);
    }
}

__global__ void map_kernel(const float* __restrict__ sim) {
    int e = threadIdx.x;
    if (e < NE) {
        d_cnt[e] = 0;
        int mask = d_mask;
        int m;
        if ((mask >> e) & 1) {
            m = e;
        } else {
            float best = -INFINITY; int bj = -1;
#pragma unroll
            for (int j = 0; j < NE; ++j) {
                if ((mask >> j) & 1) {
                    float s = sim[e * NE + j];
                    if (s > best) { best = s; bj = j; }
                }
            }
            m = (bj >= 0 && best >= 0.7f) ? bj : e;
        }
        d_map[e] = m;
    }
}

__global__ void assign_kernel() {
    int n = blockIdx.x * blockDim.x + threadIdx.x;
    if (n >= N_TOK) return;
    int   i0 = d_top_i[2 * n],     i1 = d_top_i[2 * n + 1];
    float w0 = d_top_w[2 * n],     w1 = d_top_w[2 * n + 1];
    int   e0 = d_map[i0],          e1 = d_map[i1];

    if (e0 == e1) {
        int idx = atomicAdd(&d_cnt[e0], 1);
        int s   = e0 * N_TOK + idx;
        d_tok[s] = n;
        d_pair_slot[2 * n]     = s;   d_pair_w[2 * n]     = w0 + w1;
        d_pair_slot[2 * n + 1] = -1;  d_pair_w[2 * n + 1] = 0.f;
    } else {
        int idx0 = atomicAdd(&d_cnt[e0], 1);
        int idx1 = atomicAdd(&d_cnt[e1], 1);
        int s0 = e0 * N_TOK + idx0, s1 = e1 * N_TOK + idx1;
        d_tok[s0] = n;
        d_tok[s1] = n;
        d_pair_slot[2 * n]     = s0;  d_pair_w[2 * n]     = w0;
        d_pair_slot[2 * n + 1] = s1;  d_pair_w[2 * n + 1] = w1;
    }
}

// ---------------- tensor-core GEMM ------------------------------------------
// C[m,j] = sum_k A[m,k] * W[e,j,k]   (both K-major), fp32 in/out.
// bf16 hi/lo split: per product hi*hi + hi*lo + lo*hi (3 MMAs, fp32 accum).
#define BM 128
#define BN 128
#define BK 32
#define LDK 40                       // halves per SMEM row (5 x 16B: conflict-free ldmatrix)
#define ASZ (128 * LDK * 2)          // 10240 bytes per bf16 tile array
#define BUFSZ (4 * ASZ)              // A_hi, A_lo, B_hi, B_lo
#define SMEM_BYTES (2 * BUFSZ)       // double buffered: 81920

#define LDSM4(r, addr) \
    asm volatile("ldmatrix.sync.aligned.m8n8.x4.shared.b16 {%0,%1,%2,%3}, [%4];" \
        : "=r"((r)[0]), "=r"((r)[1]), "=r"((r)[2]), "=r"((r)[3]) : "r"(addr))

#define MMA_BF16(c, a, b0, b1) \
    asm volatile("mma.sync.aligned.m16n8k16.row.col.f32.bf16.bf16.f32 " \
        "{%0,%1,%2,%3},{%4,%5,%6,%7},{%8,%9},{%0,%1,%2,%3};" \
        : "+f"((c)[0]), "+f"((c)[1]), "+f"((c)[2]), "+f"((c)[3]) \
        : "r"((a)[0]), "r"((a)[1]), "r"((a)[2]), "r"((a)[3]), "r"(b0), "r"(b1))

__device__ __forceinline__ uint32_t split_pair(float x, float y, uint32_t& lo) {
    __nv_bfloat162 h = __float22bfloat162_rn(make_float2(x, y));
    float lx = x - __bfloat162float(h.x);
    float ly = y - __bfloat162float(h.y);
    __nv_bfloat162 l = __float22bfloat162_rn(make_float2(lx, ly));
    lo = *reinterpret_cast<uint32_t*>(&l);
    return *reinterpret_cast<uint32_t*>(&h);
}

__device__ __forceinline__ void cvt_sts16(unsigned char* hip, unsigned char* lop,
                                          const float4* v) {
    uint32_t h[8], l[8];
#pragma unroll
    for (int q = 0; q < 4; ++q) {
        h[q * 2 + 0] = split_pair(v[q].x, v[q].y, l[q * 2 + 0]);
        h[q * 2 + 1] = split_pair(v[q].z, v[q].w, l[q * 2 + 1]);
    }
    *(uint4*)(hip)      = make_uint4(h[0], h[1], h[2], h[3]);
    *(uint4*)(hip + 16) = make_uint4(h[4], h[5], h[6], h[7]);
    *(uint4*)(lop)      = make_uint4(l[0], l[1], l[2], l[3]);
    *(uint4*)(lop + 16) = make_uint4(l[4], l[5], l[6], l[7]);
}

template <bool FIRST>
__global__ __launch_bounds__(256)
void gemm_tc(const float* __restrict__ Ain, const float* __restrict__ W) {
    constexpr int NCOLS = FIRST ? (2 * FDIM) : HDIM;
    constexpr int KDIM  = FIRST ? HDIM : FDIM;
    constexpr int KT    = KDIM / BK;

    int e   = blockIdx.z;
    int cnt = d_cnt[e];
    int m0  = blockIdx.y * BM;
    if (m0 >= cnt) return;
    int j0  = blockIdx.x * BN;

    extern __shared__ __align__(16) unsigned char smem[];
    uint32_t sbase = (uint32_t)__cvta_generic_to_shared(smem);

    int tid  = threadIdx.x;
    int lane = tid & 31;
    int wid  = tid >> 5;
    int warp_m = wid & 3;      // 4 warps over M (32 rows each)
    int warp_n = wid >> 2;     // 2 warps over N (64 cols each)

    // ------- loader setup: each thread owns one row x 16 consecutive k ------
    int  m_l  = tid >> 1;
    int  half = tid & 1;
    int  am   = m0 + m_l;
    bool avalid = (am < cnt);
    const float* arow;
    if (FIRST) {
        int t = avalid ? d_tok[e * N_TOK + am] : 0;
        arow  = Ain + (size_t)t * KDIM + half * 16;
    } else {
        arow  = d_hmid + (size_t)(e * N_TOK + (avalid ? am : 0)) * KDIM + half * 16;
    }
    const float* brow = W + (size_t)e * NCOLS * KDIM
                          + (size_t)(j0 + m_l) * KDIM + half * 16;
    int sts_off = (m_l * LDK + half * 16) * 2;   // byte offset within a tile array

    float4 pa[4], pb[4];
    const float4 z4 = make_float4(0.f, 0.f, 0.f, 0.f);

    // prologue: k-tile 0 -> buffer 0
#pragma unroll
    for (int q = 0; q < 4; ++q) {
        pa[q] = avalid ? *(const float4*)(arow + q * 4) : z4;
        pb[q] = *(const float4*)(brow + q * 4);
    }
    cvt_sts16(smem + sts_off,            smem + ASZ + sts_off,     pa);
    cvt_sts16(smem + 2 * ASZ + sts_off,  smem + 3 * ASZ + sts_off, pb);
    __syncthreads();

    // ------- compute setup ---------------------------------------------------
    float acc[2][8][4];
#pragma unroll
    for (int i = 0; i < 2; ++i)
#pragma unroll
        for (int j = 0; j < 8; ++j)
#pragma unroll
            for (int q = 0; q < 4; ++q) acc[i][j][q] = 0.f;

    // lane-dependent ldmatrix offsets (bytes, within a buffer)
    uint32_t a_lane = ((warp_m * 32 + (lane & 15)) * LDK + ((lane >> 4) * 8)) * 2;
    uint32_t b_lane = 2 * ASZ +
        ((warp_n * 64 + (lane & 7) + (((lane >> 4) & 1) * 8)) * LDK +
         (((lane >> 3) & 1) * 8)) * 2;

    uint32_t bufo = 0;
    for (int kt = 0; kt < KT; ++kt) {
        bool more = (kt + 1 < KT);
        if (more) {
            int kb = (kt + 1) * BK;
#pragma unroll
            for (int q = 0; q < 4; ++q) {
                pa[q] = avalid ? *(const float4*)(arow + kb + q * 4) : z4;
                pb[q] = *(const float4*)(brow + kb + q * 4);
            }
        }

#pragma unroll
        for (int ks = 0; ks < 2; ++ks) {
            uint32_t koff = ks * 16 * 2;
            uint32_t ah[2][4];
            uint32_t al[2][4];
#pragma unroll
            for (int mt = 0; mt < 2; ++mt) {
                uint32_t aaddr = sbase + bufo + a_lane + (mt * 16 * LDK) * 2 + koff;
                LDSM4(ah[mt], aaddr);
                LDSM4(al[mt], aaddr + ASZ);
            }
#pragma unroll
            for (int ng = 0; ng < 4; ++ng) {
                uint32_t baddr = sbase + bufo + b_lane + (ng * 16 * LDK) * 2 + koff;
                uint32_t bh[4];
                uint32_t bl[4];
                LDSM4(bh, baddr);
                LDSM4(bl, baddr + ASZ);
                // pass 1: hi*hi
#pragma unroll
                for (int mt = 0; mt < 2; ++mt) {
                    MMA_BF16(acc[mt][2 * ng],     ah[mt], bh[0], bh[1]);
                    MMA_BF16(acc[mt][2 * ng + 1], ah[mt], bh[2], bh[3]);
                }
                // pass 2: hi*lo
#pragma unroll
                for (int mt = 0; mt < 2; ++mt) {
                    MMA_BF16(acc[mt][2 * ng],     ah[mt], bl[0], bl[1]);
                    MMA_BF16(acc[mt][2 * ng + 1], ah[mt], bl[2], bl[3]);
                }
                // pass 3: lo*hi
#pragma unroll
                for (int mt = 0; mt < 2; ++mt) {
                    MMA_BF16(acc[mt][2 * ng],     al[mt], bh[0], bh[1]);
                    MMA_BF16(acc[mt][2 * ng + 1], al[mt], bh[2], bh[3]);
                }
            }
        }

        if (more) {
            uint32_t nb = bufo ^ BUFSZ;
            cvt_sts16(smem + nb + sts_off,           smem + nb + ASZ + sts_off,     pa);
            cvt_sts16(smem + nb + 2 * ASZ + sts_off, smem + nb + 3 * ASZ + sts_off, pb);
            __syncthreads();
            bufo = nb;
        }
    }

    // ------- epilogue ---------------------------------------------------------
    float* C = FIRST ? d_gu : d_y;
    int r_base = m0 + warp_m * 32 + (lane >> 2);
    int c_base = j0 + warp_n * 64 + (lane & 3) * 2;
#pragma unroll
    for (int mt = 0; mt < 2; ++mt) {
#pragma unroll
        for (int nt = 0; nt < 8; ++nt) {
            int r0 = r_base + mt * 16;
            int c  = c_base + nt * 8;
            if (r0 < cnt) {
                float* p = C + (size_t)(e * N_TOK + r0) * NCOLS + c;
                *(float2*)p = make_float2(acc[mt][nt][0], acc[mt][nt][1]);
            }
            if (r0 + 8 < cnt) {
                float* p = C + (size_t)(e * N_TOK + r0 + 8) * NCOLS + c;
                *(float2*)p = make_float2(acc[mt][nt][2], acc[mt][nt][3]);
            }
        }
    }
}

// hmid = silu(gate) * up
__global__ void silu_kernel() {
    int e = blockIdx.z;
    int m = blockIdx.y;
    if (m >= d_cnt[e]) return;
    size_t slot = (size_t)(e * N_TOK + m);
    int q = threadIdx.x;
    const float4 g4 = *(const float4*)&d_gu[slot * (2 * FDIM) + q * 4];
    const float4 u4 = *(const float4*)&d_gu[slot * (2 * FDIM) + FDIM + q * 4];
    float4 r;
    r.x = (g4.x / (1.f + expf(-g4.x))) * u4.x;
    r.y = (g4.y / (1.f + expf(-g4.y))) * u4.y;
    r.z = (g4.z / (1.f + expf(-g4.z))) * u4.z;
    r.w = (g4.w / (1.f + expf(-g4.w))) * u4.w;
    *(float4*)&d_hmid[slot * FDIM + q * 4] = r;
}

// out[n] = w0 * y[slot0] + w1 * y[slot1]
__global__ void combine_kernel(float* __restrict__ out) {
    int n = blockIdx.x;
    int q = threadIdx.x;
    int   s0 = d_pair_slot[2 * n],     s1 = d_pair_slot[2 * n + 1];
    float w0 = d_pair_w[2 * n],        w1 = d_pair_w[2 * n + 1];

    float4 a = *(const float4*)&d_y[(size_t)s0 * HDIM + q * 4];
    float4 r;
    r.x = w0 * a.x; r.y = w0 * a.y; r.z = w0 * a.z; r.w = w0 * a.w;
    if (s1 >= 0) {
        float4 b = *(const float4*)&d_y[(size_t)s1 * HDIM + q * 4];
        r.x = fmaf(w1, b.x, r.x); r.y = fmaf(w1, b.y, r.y);
        r.z = fmaf(w1, b.z, r.z); r.w = fmaf(w1, b.w, r.w);
    }
    *(float4*)&out[(size_t)n * HDIM + q * 4] = r;
}

// ---------------- launcher ---------------------------------------------------
extern "C" void kernel_launch(void* const* d_in, const int* in_sizes, int n_in,
                              void* d_out, int out_size) {
    const float* x   = (const float*)d_in[0];
    const float* gw  = (const float*)d_in[1];
    const float* gup = (const float*)d_in[2];
    const float* dwn = (const float*)d_in[3];
    const float* sim = (const float*)d_in[4];
    float* out = (float*)d_out;

    cudaFuncSetAttribute(gemm_tc<true>,
                         cudaFuncAttributeMaxDynamicSharedMemorySize, SMEM_BYTES);
    cudaFuncSetAttribute(gemm_tc<false>,
                         cudaFuncAttributeMaxDynamicSharedMemorySize, SMEM_BYTES);

    init_kernel<<<1, 32>>>();
    router_kernel<<<N_TOK, 128>>>(x, gw);
    map_kernel<<<1, 32>>>(sim);
    assign_kernel<<<(N_TOK + 255) / 256, 256>>>();

    gemm_tc<true><<<dim3((2 * FDIM) / BN, N_TOK / BM, NE), 256, SMEM_BYTES>>>(x, gup);
    silu_kernel<<<dim3(1, N_TOK, NE), 256>>>();
    gemm_tc<false><<<dim3(HDIM / BN, N_TOK / BM, NE), 256, SMEM_BYTES>>>(nullptr, dwn);
    combine_kernel<<<N_TOK, 256>>>(out);
}

// round 11
// speedup vs baseline: 2.2564x; 1.0192x over previous
#include <cuda_runtime.h>
#include <cuda_bf16.h>
#include <math.h>
#include <stdint.h>

#define N_TOK 2048
#define HDIM  1024
#define FDIM  1024
#define NE    8
#define TOPK  2
#define SLOTS (NE * N_TOK)

// ---------------- device scratch (static: no allocations allowed) -----------
__device__ int   d_mask;
__device__ int   d_cnt[NE];
__device__ int   d_map[NE];
__device__ int   d_tok[SLOTS];
__device__ int   d_top_i[N_TOK * TOPK];
__device__ float d_top_w[N_TOK * TOPK];
__device__ int   d_pair_slot[N_TOK * TOPK];
__device__ float d_pair_w[N_TOK * TOPK];
__device__ __nv_bfloat16 d_hmid_h[(size_t)SLOTS * FDIM];   // 32 MB
__device__ __nv_bfloat16 d_hmid_l[(size_t)SLOTS * FDIM];   // 32 MB
__device__ float d_y   [(size_t)SLOTS * HDIM];             // 64 MB

// ---------------- tiny setup kernels ----------------------------------------
__global__ void init_kernel() {
    if (threadIdx.x == 0) d_mask = 0;
}

__global__ void router_kernel(const float* __restrict__ x,
                              const float* __restrict__ gw) {
    int n   = blockIdx.x;
    int tid = threadIdx.x;
    const float* xr = x + (size_t)n * HDIM;

    float p[NE];
#pragma unroll
    for (int e = 0; e < NE; ++e) p[e] = 0.f;

    for (int h = tid; h < HDIM; h += 128) {
        float xv = xr[h];
#pragma unroll
        for (int e = 0; e < NE; ++e)
            p[e] = fmaf(xv, gw[e * HDIM + h], p[e]);
    }
#pragma unroll
    for (int e = 0; e < NE; ++e)
#pragma unroll
        for (int o = 16; o > 0; o >>= 1)
            p[e] += __shfl_xor_sync(0xffffffffu, p[e], o);

    __shared__ float sh[NE][4];
    int w = tid >> 5, l = tid & 31;
    if (l == 0)
#pragma unroll
        for (int e = 0; e < NE; ++e) sh[e][w] = p[e];
    __syncthreads();

    if (tid == 0) {
        float lg[NE];
#pragma unroll
        for (int e = 0; e < NE; ++e)
            lg[e] = sh[e][0] + sh[e][1] + sh[e][2] + sh[e][3];
        float mx = lg[0];
#pragma unroll
        for (int e = 1; e < NE; ++e) mx = fmaxf(mx, lg[e]);
        float pr[NE], s = 0.f;
#pragma unroll
        for (int e = 0; e < NE; ++e) { pr[e] = expf(lg[e] - mx); s += pr[e]; }
        float inv = 1.f / s;
#pragma unroll
        for (int e = 0; e < NE; ++e) pr[e] *= inv;

        int i0 = 0;
#pragma unroll
        for (int e = 1; e < NE; ++e) if (pr[e] > pr[i0]) i0 = e;
        int i1 = -1;
#pragma unroll
        for (int e = 0; e < NE; ++e)
            if (e != i0 && (i1 < 0 || pr[e] > pr[i1])) i1 = e;

        float w0 = pr[i0], w1 = pr[i1];
        float den = fmaxf(w0 + w1, 1e-12f);
        w0 /= den; w1 /= den;

        d_top_i[2 * n]     = i0;
        d_top_i[2 * n + 1] = i1;
        d_top_w[2 * n]     = w0;
        d_top_w[2 * n + 1] = w1;
        atomicOr(&d_mask, 1 << i0);
    }
}

__global__ void map_kernel(const float* __restrict__ sim) {
    int e = threadIdx.x;
    if (e < NE) {
        d_cnt[e] = 0;
        int mask = d_mask;
        int m;
        if ((mask >> e) & 1) {
            m = e;
        } else {
            float best = -INFINITY; int bj = -1;
#pragma unroll
            for (int j = 0; j < NE; ++j) {
                if ((mask >> j) & 1) {
                    float s = sim[e * NE + j];
                    if (s > best) { best = s; bj = j; }
                }
            }
            m = (bj >= 0 && best >= 0.7f) ? bj : e;
        }
        d_map[e] = m;
    }
}

__global__ void assign_kernel() {
    int n = blockIdx.x * blockDim.x + threadIdx.x;
    if (n >= N_TOK) return;
    int   i0 = d_top_i[2 * n],     i1 = d_top_i[2 * n + 1];
    float w0 = d_top_w[2 * n],     w1 = d_top_w[2 * n + 1];
    int   e0 = d_map[i0],          e1 = d_map[i1];

    if (e0 == e1) {
        int idx = atomicAdd(&d_cnt[e0], 1);
        int s   = e0 * N_TOK + idx;
        d_tok[s] = n;
        d_pair_slot[2 * n]     = s;   d_pair_w[2 * n]     = w0 + w1;
        d_pair_slot[2 * n + 1] = -1;  d_pair_w[2 * n + 1] = 0.f;
    } else {
        int idx0 = atomicAdd(&d_cnt[e0], 1);
        int idx1 = atomicAdd(&d_cnt[e1], 1);
        int s0 = e0 * N_TOK + idx0, s1 = e1 * N_TOK + idx1;
        d_tok[s0] = n;
        d_tok[s1] = n;
        d_pair_slot[2 * n]     = s0;  d_pair_w[2 * n]     = w0;
        d_pair_slot[2 * n + 1] = s1;  d_pair_w[2 * n + 1] = w1;
    }
}

// ---------------- tensor-core GEMM common -----------------------------------
#define BM 128
#define BK 32
#define LDK 40                       // halves per SMEM row (5 x 16B: conflict-free ldmatrix)
#define ASZ (128 * LDK * 2)          // 10240 bytes per bf16 tile array
#define BUFSZ (4 * ASZ)              // A_hi, A_lo, B_hi, B_lo
#define SMEM_BYTES (2 * BUFSZ)       // double buffered: 81920

#define LDSM4(r, addr) \
    asm volatile("ldmatrix.sync.aligned.m8n8.x4.shared.b16 {%0,%1,%2,%3}, [%4];" \
        : "=r"((r)[0]), "=r"((r)[1]), "=r"((r)[2]), "=r"((r)[3]) : "r"(addr))

#define MMA_BF16(c, a, b0, b1) \
    asm volatile("mma.sync.aligned.m16n8k16.row.col.f32.bf16.bf16.f32 " \
        "{%0,%1,%2,%3},{%4,%5,%6,%7},{%8,%9},{%0,%1,%2,%3};" \
        : "+f"((c)[0]), "+f"((c)[1]), "+f"((c)[2]), "+f"((c)[3]) \
        : "r"((a)[0]), "r"((a)[1]), "r"((a)[2]), "r"((a)[3]), "r"(b0), "r"(b1))

__device__ __forceinline__ uint32_t split_pair(float x, float y, uint32_t& lo) {
    __nv_bfloat162 h = __float22bfloat162_rn(make_float2(x, y));
    float lx = x - __bfloat162float(h.x);
    float ly = y - __bfloat162float(h.y);
    __nv_bfloat162 l = __float22bfloat162_rn(make_float2(lx, ly));
    lo = *reinterpret_cast<uint32_t*>(&l);
    return *reinterpret_cast<uint32_t*>(&h);
}

__device__ __forceinline__ void cvt_sts16(unsigned char* hip, unsigned char* lop,
                                          const float4* v) {
    uint32_t h[8], l[8];
#pragma unroll
    for (int q = 0; q < 4; ++q) {
        h[q * 2 + 0] = split_pair(v[q].x, v[q].y, l[q * 2 + 0]);
        h[q * 2 + 1] = split_pair(v[q].z, v[q].w, l[q * 2 + 1]);
    }
    *(uint4*)(hip)      = make_uint4(h[0], h[1], h[2], h[3]);
    *(uint4*)(hip + 16) = make_uint4(h[4], h[5], h[6], h[7]);
    *(uint4*)(lop)      = make_uint4(l[0], l[1], l[2], l[3]);
    *(uint4*)(lop + 16) = make_uint4(l[4], l[5], l[6], l[7]);
}

__device__ __forceinline__ float silu_f(float g) {
    return g / (1.f + expf(-g));
}

// ---------------- GEMM1 fused: x @ gate_up^T -> silu(g)*u -> hmid (bf16 hi/lo)
// CTA: 128 tokens x 64 hmid cols. B tile = 128 W rows arranged per 64-row warp
// span as [32 gate rows | 32 up rows] for the SAME output columns.
__global__ __launch_bounds__(256)
void gemm1_fused(const float* __restrict__ Ain, const float* __restrict__ W) {
    constexpr int KDIM = HDIM;
    constexpr int KT   = KDIM / BK;

    int e   = blockIdx.z;
    int cnt = d_cnt[e];
    int m0  = blockIdx.y * BM;
    if (m0 >= cnt) return;
    int j0  = blockIdx.x * 64;           // output hmid column base

    extern __shared__ __align__(16) unsigned char smem[];
    uint32_t sbase = (uint32_t)__cvta_generic_to_shared(smem);

    int tid  = threadIdx.x;
    int lane = tid & 31;
    int wid  = tid >> 5;
    int warp_m = wid & 3;
    int warp_n = wid >> 2;

    // loader: thread owns one SMEM row x 16 consecutive k
    int  m_l  = tid >> 1;
    int  half = tid & 1;
    int  am   = m0 + m_l;
    bool avalid = (am < cnt);
    int t = avalid ? d_tok[e * N_TOK + am] : 0;
    const float* arow = Ain + (size_t)t * KDIM + half * 16;

    // B row mapping: within 64-row warp span, first 32 = gate, next 32 = up.
    int wn = m_l >> 6;                    // which warp_n span this row feeds
    int q  = m_l & 63;
    int wrow = (q < 32) ? (j0 + wn * 32 + q)
                        : (FDIM + j0 + wn * 32 + (q - 32));
    const float* brow = W + (size_t)e * (2 * FDIM) * KDIM
                          + (size_t)wrow * KDIM + half * 16;
    int sts_off = (m_l * LDK + half * 16) * 2;

    float4 pa[4], pb[4];
    const float4 z4 = make_float4(0.f, 0.f, 0.f, 0.f);

#pragma unroll
    for (int qq = 0; qq < 4; ++qq) {
        pa[qq] = avalid ? *(const float4*)(arow + qq * 4) : z4;
        pb[qq] = *(const float4*)(brow + qq * 4);
    }
    cvt_sts16(smem + sts_off,            smem + ASZ + sts_off,     pa);
    cvt_sts16(smem + 2 * ASZ + sts_off,  smem + 3 * ASZ + sts_off, pb);
    __syncthreads();

    float acc[2][8][4];
#pragma unroll
    for (int i = 0; i < 2; ++i)
#pragma unroll
        for (int j = 0; j < 8; ++j)
#pragma unroll
            for (int qq = 0; qq < 4; ++qq) acc[i][j][qq] = 0.f;

    uint32_t a_lane = ((warp_m * 32 + (lane & 15)) * LDK + ((lane >> 4) * 8)) * 2;
    uint32_t b_lane = 2 * ASZ +
        ((warp_n * 64 + (lane & 7) + (((lane >> 4) & 1) * 8)) * LDK +
         (((lane >> 3) & 1) * 8)) * 2;

    uint32_t bufo = 0;
    for (int kt = 0; kt < KT; ++kt) {
        bool more = (kt + 1 < KT);
        if (more) {
            int kb = (kt + 1) * BK;
#pragma unroll
            for (int qq = 0; qq < 4; ++qq) {
                pa[qq] = avalid ? *(const float4*)(arow + kb + qq * 4) : z4;
                pb[qq] = *(const float4*)(brow + kb + qq * 4);
            }
        }

#pragma unroll
        for (int ks = 0; ks < 2; ++ks) {
            uint32_t koff = ks * 16 * 2;
            uint32_t ah[2][4];
            uint32_t al[2][4];
#pragma unroll
            for (int mt = 0; mt < 2; ++mt) {
                uint32_t aaddr = sbase + bufo + a_lane + (mt * 16 * LDK) * 2 + koff;
                LDSM4(ah[mt], aaddr);
                LDSM4(al[mt], aaddr + ASZ);
            }
#pragma unroll
            for (int ng = 0; ng < 4; ++ng) {
                uint32_t baddr = sbase + bufo + b_lane + (ng * 16 * LDK) * 2 + koff;
                uint32_t bh[4];
                uint32_t bl[4];
                LDSM4(bh, baddr);
                LDSM4(bl, baddr + ASZ);
#pragma unroll
                for (int mt = 0; mt < 2; ++mt) {
                    MMA_BF16(acc[mt][2 * ng],     ah[mt], bh[0], bh[1]);
                    MMA_BF16(acc[mt][2 * ng + 1], ah[mt], bh[2], bh[3]);
                }
#pragma unroll
                for (int mt = 0; mt < 2; ++mt) {
                    MMA_BF16(acc[mt][2 * ng],     ah[mt], bl[0], bl[1]);
                    MMA_BF16(acc[mt][2 * ng + 1], ah[mt], bl[2], bl[3]);
                }
#pragma unroll
                for (int mt = 0; mt < 2; ++mt) {
                    MMA_BF16(acc[mt][2 * ng],     al[mt], bh[0], bh[1]);
                    MMA_BF16(acc[mt][2 * ng + 1], al[mt], bh[2], bh[3]);
                }
            }
        }

        if (more) {
            uint32_t nb = bufo ^ BUFSZ;
            cvt_sts16(smem + nb + sts_off,           smem + nb + ASZ + sts_off,     pa);
            cvt_sts16(smem + nb + 2 * ASZ + sts_off, smem + nb + 3 * ASZ + sts_off, pb);
            __syncthreads();
            bufo = nb;
        }
    }

    // epilogue: silu(gate)*up, split to bf16 hi/lo, store hmid
    // acc[mt][0..3] = gate cols (warp span 0..31), acc[mt][4..7] = up same cols
    int r_base = m0 + warp_m * 32 + (lane >> 2);
    int c_base = j0 + warp_n * 32 + (lane & 3) * 2;
#pragma unroll
    for (int mt = 0; mt < 2; ++mt) {
#pragma unroll
        for (int nt = 0; nt < 4; ++nt) {
            int r0 = r_base + mt * 16;
            int c  = c_base + nt * 8;
            float* g = acc[mt][nt];
            float* u = acc[mt][nt + 4];
            if (r0 < cnt) {
                float h0 = silu_f(g[0]) * u[0];
                float h1 = silu_f(g[1]) * u[1];
                uint32_t lo, hi = split_pair(h0, h1, lo);
                size_t off = (size_t)(e * N_TOK + r0) * FDIM + c;
                *(uint32_t*)&d_hmid_h[off] = hi;
                *(uint32_t*)&d_hmid_l[off] = lo;
            }
            if (r0 + 8 < cnt) {
                float h2 = silu_f(g[2]) * u[2];
                float h3 = silu_f(g[3]) * u[3];
                uint32_t lo, hi = split_pair(h2, h3, lo);
                size_t off = (size_t)(e * N_TOK + r0 + 8) * FDIM + c;
                *(uint32_t*)&d_hmid_h[off] = hi;
                *(uint32_t*)&d_hmid_l[off] = lo;
            }
        }
    }
}

// ---------------- GEMM2: hmid(bf16 hi/lo) @ down^T -> y (fp32) ---------------
__global__ __launch_bounds__(256)
void gemm2_tc(const float* __restrict__ W) {
    constexpr int NCOLS = HDIM;
    constexpr int KDIM  = FDIM;
    constexpr int KT    = KDIM / BK;

    int e   = blockIdx.z;
    int cnt = d_cnt[e];
    int m0  = blockIdx.y * BM;
    if (m0 >= cnt) return;
    int j0  = blockIdx.x * 128;

    extern __shared__ __align__(16) unsigned char smem[];
    uint32_t sbase = (uint32_t)__cvta_generic_to_shared(smem);

    int tid  = threadIdx.x;
    int lane = tid & 31;
    int wid  = tid >> 5;
    int warp_m = wid & 3;
    int warp_n = wid >> 2;

    int  m_l  = tid >> 1;
    int  half = tid & 1;
    int  am   = m0 + m_l;
    bool avalid = (am < cnt);
    size_t slotrow = (size_t)(e * N_TOK + (avalid ? am : 0));
    const __nv_bfloat16* arow_h = d_hmid_h + slotrow * KDIM + half * 16;
    const __nv_bfloat16* arow_l = d_hmid_l + slotrow * KDIM + half * 16;
    const float* brow = W + (size_t)e * NCOLS * KDIM
                          + (size_t)(j0 + m_l) * KDIM + half * 16;
    int sts_off = (m_l * LDK + half * 16) * 2;

    uint4 pah[2], pal[2];
    float4 pb[4];
    const uint4  zu = make_uint4(0, 0, 0, 0);
    const float4 z4 = make_float4(0.f, 0.f, 0.f, 0.f);

    pah[0] = avalid ? *(const uint4*)(arow_h)     : zu;
    pah[1] = avalid ? *(const uint4*)(arow_h + 8) : zu;
    pal[0] = avalid ? *(const uint4*)(arow_l)     : zu;
    pal[1] = avalid ? *(const uint4*)(arow_l + 8) : zu;
#pragma unroll
    for (int qq = 0; qq < 4; ++qq) pb[qq] = *(const float4*)(brow + qq * 4);

    *(uint4*)(smem + sts_off)            = pah[0];
    *(uint4*)(smem + sts_off + 16)       = pah[1];
    *(uint4*)(smem + ASZ + sts_off)      = pal[0];
    *(uint4*)(smem + ASZ + sts_off + 16) = pal[1];
    cvt_sts16(smem + 2 * ASZ + sts_off, smem + 3 * ASZ + sts_off, pb);
    __syncthreads();

    float acc[2][8][4];
#pragma unroll
    for (int i = 0; i < 2; ++i)
#pragma unroll
        for (int j = 0; j < 8; ++j)
#pragma unroll
            for (int qq = 0; qq < 4; ++qq) acc[i][j][qq] = 0.f;

    uint32_t a_lane = ((warp_m * 32 + (lane & 15)) * LDK + ((lane >> 4) * 8)) * 2;
    uint32_t b_lane = 2 * ASZ +
        ((warp_n * 64 + (lane & 7) + (((lane >> 4) & 1) * 8)) * LDK +
         (((lane >> 3) & 1) * 8)) * 2;

    uint32_t bufo = 0;
    for (int kt = 0; kt < KT; ++kt) {
        bool more = (kt + 1 < KT);
        if (more) {
            int kb = (kt + 1) * BK;
            pah[0] = avalid ? *(const uint4*)(arow_h + kb)     : zu;
            pah[1] = avalid ? *(const uint4*)(arow_h + kb + 8) : zu;
            pal[0] = avalid ? *(const uint4*)(arow_l + kb)     : zu;
            pal[1] = avalid ? *(const uint4*)(arow_l + kb + 8) : zu;
#pragma unroll
            for (int qq = 0; qq < 4; ++qq)
                pb[qq] = *(const float4*)(brow + kb + qq * 4);
        }

#pragma unroll
        for (int ks = 0; ks < 2; ++ks) {
            uint32_t koff = ks * 16 * 2;
            uint32_t ah[2][4];
            uint32_t al[2][4];
#pragma unroll
            for (int mt = 0; mt < 2; ++mt) {
                uint32_t aaddr = sbase + bufo + a_lane + (mt * 16 * LDK) * 2 + koff;
                LDSM4(ah[mt], aaddr);
                LDSM4(al[mt], aaddr + ASZ);
            }
#pragma unroll
            for (int ng = 0; ng < 4; ++ng) {
                uint32_t baddr = sbase + bufo + b_lane + (ng * 16 * LDK) * 2 + koff;
                uint32_t bh[4];
                uint32_t bl[4];
                LDSM4(bh, baddr);
                LDSM4(bl, baddr + ASZ);
#pragma unroll
                for (int mt = 0; mt < 2; ++mt) {
                    MMA_BF16(acc[mt][2 * ng],     ah[mt], bh[0], bh[1]);
                    MMA_BF16(acc[mt][2 * ng + 1], ah[mt], bh[2], bh[3]);
                }
#pragma unroll
                for (int mt = 0; mt < 2; ++mt) {
                    MMA_BF16(acc[mt][2 * ng],     ah[mt], bl[0], bl[1]);
                    MMA_BF16(acc[mt][2 * ng + 1], ah[mt], bl[2], bl[3]);
                }
#pragma unroll
                for (int mt = 0; mt < 2; ++mt) {
                    MMA_BF16(acc[mt][2 * ng],     al[mt], bh[0], bh[1]);
                    MMA_BF16(acc[mt][2 * ng + 1], al[mt], bh[2], bh[3]);
                }
            }
        }

        if (more) {
            uint32_t nb = bufo ^ BUFSZ;
            *(uint4*)(smem + nb + sts_off)            = pah[0];
            *(uint4*)(smem + nb + sts_off + 16)       = pah[1];
            *(uint4*)(smem + nb + ASZ + sts_off)      = pal[0];
            *(uint4*)(smem + nb + ASZ + sts_off + 16) = pal[1];
            cvt_sts16(smem + nb + 2 * ASZ + sts_off, smem + nb + 3 * ASZ + sts_off, pb);
            __syncthreads();
            bufo = nb;
        }
    }

    int r_base = m0 + warp_m * 32 + (lane >> 2);
    int c_base = j0 + warp_n * 64 + (lane & 3) * 2;
#pragma unroll
    for (int mt = 0; mt < 2; ++mt) {
#pragma unroll
        for (int nt = 0; nt < 8; ++nt) {
            int r0 = r_base + mt * 16;
            int c  = c_base + nt * 8;
            if (r0 < cnt) {
                float* p = d_y + (size_t)(e * N_TOK + r0) * NCOLS + c;
                *(float2*)p = make_float2(acc[mt][nt][0], acc[mt][nt][1]);
            }
            if (r0 + 8 < cnt) {
                float* p = d_y + (size_t)(e * N_TOK + r0 + 8) * NCOLS + c;
                *(float2*)p = make_float2(acc[mt][nt][2], acc[mt][nt][3]);
            }
        }
    }
}

// out[n] = w0 * y[slot0] + w1 * y[slot1]
__global__ void combine_kernel(float* __restrict__ out) {
    int n = blockIdx.x;
    int q = threadIdx.x;
    int   s0 = d_pair_slot[2 * n],     s1 = d_pair_slot[2 * n + 1];
    float w0 = d_pair_w[2 * n],        w1 = d_pair_w[2 * n + 1];

    float4 a = *(const float4*)&d_y[(size_t)s0 * HDIM + q * 4];
    float4 r;
    r.x = w0 * a.x; r.y = w0 * a.y; r.z = w0 * a.z; r.w = w0 * a.w;
    if (s1 >= 0) {
        float4 b = *(const float4*)&d_y[(size_t)s1 * HDIM + q * 4];
        r.x = fmaf(w1, b.x, r.x); r.y = fmaf(w1, b.y, r.y);
        r.z = fmaf(w1, b.z, r.z); r.w = fmaf(w1, b.w, r.w);
    }
    *(float4*)&out[(size_t)n * HDIM + q * 4] = r;
}

// ---------------- launcher ---------------------------------------------------
extern "C" void kernel_launch(void* const* d_in, const int* in_sizes, int n_in,
                              void* d_out, int out_size) {
    const float* x   = (const float*)d_in[0];
    const float* gw  = (const float*)d_in[1];
    const float* gup = (const float*)d_in[2];
    const float* dwn = (const float*)d_in[3];
    const float* sim = (const float*)d_in[4];
    float* out = (float*)d_out;

    cudaFuncSetAttribute(gemm1_fused,
                         cudaFuncAttributeMaxDynamicSharedMemorySize, SMEM_BYTES);
    cudaFuncSetAttribute(gemm2_tc,
                         cudaFuncAttributeMaxDynamicSharedMemorySize, SMEM_BYTES);

    init_kernel<<<1, 32>>>();
    router_kernel<<<N_TOK, 128>>>(x, gw);
    map_kernel<<<1, 32>>>(sim);
    assign_kernel<<<(N_TOK + 255) / 256, 256>>>();

    // gemm1 fused with silu: 64 hmid cols per CTA (gate+up computed together)
    gemm1_fused<<<dim3(FDIM / 64, N_TOK / BM, NE), 256, SMEM_BYTES>>>(x, gup);
    // gemm2: y = hmid @ down^T
    gemm2_tc<<<dim3(HDIM / 128, N_TOK / BM, NE), 256, SMEM_BYTES>>>(dwn);
    combine_kernel<<<N_TOK, 256>>>(out);
}